// round 1
// baseline (speedup 1.0000x reference)
#include <cuda_runtime.h>
#include <cuda_bf16.h>
#include <math.h>

// ---------------- scratch (device globals; no allocation) ----------------
#define B_GR 16
#define N_ND 1024
#define H_IN 256
#define H2 512
#define NT (B_GR * N_ND)            // 16384
#define NEDGE (2 * (N_ND - 1) * B_GR) // 32736

__device__ __align__(16) float g_dist[B_GR * N_ND * N_ND];   // 64 MB
__device__ __align__(16) float g_n2[NT];
__device__ int   g_parent[NT];
__device__ float g_pw[NT];
__device__ int   g_cnt[NT];
__device__ int   g_indptr[NT + 1];
__device__ int   g_cursor[NT];
__device__ float g_degw[NT];
__device__ float g_dinv[NT];
__device__ int   g_adj[NEDGE];
__device__ float g_adjw[NEDGE];
__device__ __align__(16) float g_bufA[NT * H2];
__device__ __align__(16) float g_bufB[NT * H2];
__device__ float g_pooled[B_GR * H2];
__device__ float g_hd[B_GR * H_IN];

// ---------------- n2 ----------------
__global__ void n2_kernel(const float* __restrict__ x) {
    int node = blockIdx.x * 8 + (threadIdx.x >> 5);
    int lane = threadIdx.x & 31;
    const float* r = x + (size_t)node * H_IN;
    float s = 0.f;
    #pragma unroll 4
    for (int k = lane; k < H_IN; k += 32) { float v = r[k]; s += v * v; }
    #pragma unroll
    for (int o = 16; o; o >>= 1) s += __shfl_xor_sync(0xffffffffu, s, o);
    if (lane == 0) g_n2[node] = s;
}

// ---------------- distance matrix: per-graph 128x128 tiles ----------------
__global__ void dist_kernel(const float* __restrict__ X) {
    __shared__ float As[8][128];
    __shared__ float Bs[8][128];
    int g  = blockIdx.z;
    int i0 = blockIdx.y * 128, j0 = blockIdx.x * 128;
    const float* Xg = X + (size_t)g * N_ND * H_IN;
    int tid = threadIdx.x;
    int tx = tid & 15, ty = tid >> 4;
    int am = tid >> 1, ak = (tid & 1) * 4;
    const float* Ap = Xg + (size_t)(i0 + am) * H_IN + ak;
    const float* Bp = Xg + (size_t)(j0 + am) * H_IN + ak;
    float acc[8][8];
    #pragma unroll
    for (int i = 0; i < 8; i++)
        #pragma unroll
        for (int j = 0; j < 8; j++) acc[i][j] = 0.f;

    for (int kb = 0; kb < H_IN; kb += 8) {
        float4 av = *(const float4*)(Ap + kb);
        float4 bv = *(const float4*)(Bp + kb);
        As[ak + 0][am] = av.x; As[ak + 1][am] = av.y; As[ak + 2][am] = av.z; As[ak + 3][am] = av.w;
        Bs[ak + 0][am] = bv.x; Bs[ak + 1][am] = bv.y; Bs[ak + 2][am] = bv.z; Bs[ak + 3][am] = bv.w;
        __syncthreads();
        #pragma unroll
        for (int k = 0; k < 8; k++) {
            float a[8], b[8];
            *(float4*)(a)     = *(const float4*)&As[k][ty * 4];
            *(float4*)(a + 4) = *(const float4*)&As[k][64 + ty * 4];
            *(float4*)(b)     = *(const float4*)&Bs[k][tx * 4];
            *(float4*)(b + 4) = *(const float4*)&Bs[k][64 + tx * 4];
            #pragma unroll
            for (int i = 0; i < 8; i++)
                #pragma unroll
                for (int j = 0; j < 8; j++) acc[i][j] = fmaf(a[i], b[j], acc[i][j]);
        }
        __syncthreads();
    }
    float* D = g_dist + (size_t)g * N_ND * N_ND;
    #pragma unroll
    for (int i = 0; i < 8; i++) {
        int ii = (i < 4) ? ty * 4 + i : 64 + ty * 4 + i - 4;
        float n2i = g_n2[g * N_ND + i0 + ii];
        #pragma unroll
        for (int j = 0; j < 8; j++) {
            int jj = (j < 4) ? tx * 4 + j : 64 + tx * 4 + j - 4;
            float d2 = n2i + g_n2[g * N_ND + j0 + jj] - 2.0f * acc[i][j];
            D[(size_t)(i0 + ii) * N_ND + (j0 + jj)] = sqrtf(fmaxf(d2, 0.f));
        }
    }
}

// ---------------- Prim MST: one CTA per graph, 256 threads x 4 nodes ----------------
__global__ void prim_kernel() {
    int g = blockIdx.x;
    int t = threadIdx.x;                    // 0..255
    const float* D = g_dist + (size_t)g * N_ND * N_ND;
    __shared__ unsigned long long warpmin[8];
    __shared__ int s_v;
    __shared__ float s_w;

    float mind[4]; int par[4]; bool intree[4];
    {
        float4 d0 = *(const float4*)(D + t * 4);
        mind[0] = d0.x; mind[1] = d0.y; mind[2] = d0.z; mind[3] = d0.w;
        #pragma unroll
        for (int l = 0; l < 4; l++) { par[l] = 0; intree[l] = false; }
        if (t == 0) intree[0] = true;   // node 0 seeds the tree
    }
    int lane = t & 31, wid = t >> 5;

    for (int it = 0; it < N_ND - 1; ++it) {
        unsigned long long best = ~0ull;
        #pragma unroll
        for (int l = 0; l < 4; l++) {
            if (!intree[l]) {
                unsigned long long key =
                    ((unsigned long long)__float_as_uint(mind[l]) << 32) | (unsigned)(t * 4 + l);
                best = min(best, key);
            }
        }
        #pragma unroll
        for (int o = 16; o; o >>= 1)
            best = min(best, __shfl_xor_sync(0xffffffffu, best, o));
        if (lane == 0) warpmin[wid] = best;
        __syncthreads();
        if (wid == 0) {
            unsigned long long b2 = (lane < 8) ? warpmin[lane] : ~0ull;
            #pragma unroll
            for (int o = 4; o; o >>= 1)
                b2 = min(b2, __shfl_xor_sync(0xffffffffu, b2, o));
            if (lane == 0) {
                s_v = (int)(b2 & 0xffffffffu);
                s_w = __uint_as_float((unsigned)(b2 >> 32));
            }
        }
        __syncthreads();
        int v = s_v; float w = s_w;
        if ((v >> 2) == t) {
            int l = v & 3;
            g_parent[g * N_ND + v] = g * N_ND + par[l];
            g_pw[g * N_ND + v] = w;
            intree[l] = true;
        }
        float4 dv = *(const float4*)(D + (size_t)v * N_ND + t * 4);
        float dvv[4] = {dv.x, dv.y, dv.z, dv.w};
        #pragma unroll
        for (int l = 0; l < 4; l++) {
            if (dvv[l] < mind[l]) { mind[l] = dvv[l]; par[l] = v; }
        }
        __syncthreads();
    }
    if (t == 0) { g_parent[g * N_ND] = g * N_ND; g_pw[g * N_ND] = 0.f; } // root sentinel
}

// ---------------- CSR build ----------------
__global__ void zero_kernel() {
    int i = blockIdx.x * blockDim.x + threadIdx.x;
    g_cnt[i] = 0; g_degw[i] = 0.f;
}
__global__ void count_kernel() {
    int v = blockIdx.x * blockDim.x + threadIdx.x;
    if ((v & (N_ND - 1)) == 0) return;    // root has no parent edge
    int p = g_parent[v];
    float w = g_pw[v];
    atomicAdd(&g_cnt[v], 1); atomicAdd(&g_cnt[p], 1);
    atomicAdd(&g_degw[v], w); atomicAdd(&g_degw[p], w);
}
__global__ void scan_kernel() {
    __shared__ int ps[256];
    int t = threadIdx.x;
    int base = t * 64;
    int s = 0;
    for (int i = 0; i < 64; i++) s += g_cnt[base + i];
    ps[t] = s;
    __syncthreads();
    for (int off = 1; off < 256; off <<= 1) {
        int v = (t >= off) ? ps[t - off] : 0;
        __syncthreads();
        ps[t] += v;
        __syncthreads();
    }
    int run = (t == 0) ? 0 : ps[t - 1];
    for (int i = 0; i < 64; i++) {
        g_indptr[base + i] = run;
        g_cursor[base + i] = run;
        run += g_cnt[base + i];
    }
    if (t == 255) g_indptr[NT] = run;
}
__global__ void fill_kernel() {
    int v = blockIdx.x * blockDim.x + threadIdx.x;
    if ((v & (N_ND - 1)) == 0) return;
    int p = g_parent[v];
    float w = g_pw[v];
    int pos = atomicAdd(&g_cursor[v], 1);
    g_adj[pos] = p; g_adjw[pos] = w;
    int pos2 = atomicAdd(&g_cursor[p], 1);
    g_adj[pos2] = v; g_adjw[pos2] = w;
}
__global__ void dinv_kernel() {
    int i = blockIdx.x * blockDim.x + threadIdx.x;
    g_dinv[i] = rsqrtf(g_degw[i] + 1.0f);   // + self loop weight 1
}

// ---------------- SSG propagation: h = a*x + (1-a)*A_hat x ----------------
__global__ void prop_kernel(const float* __restrict__ x, float* __restrict__ h, int F) {
    int node = blockIdx.x;
    int t = threadIdx.x;              // 128
    float di = g_dinv[node];
    float cs = 0.3f + 0.7f * di * di; // alpha + (1-alpha)*dinv^2 (self loop)
    float sc = 0.7f * di;
    int beg = g_indptr[node], end = g_indptr[node + 1];
    int nf = F >> 7;                  // 2 or 4
    const float* xr = x + (size_t)node * F;
    float acc[4];
    #pragma unroll
    for (int l = 0; l < 4; l++) acc[l] = (l < nf) ? cs * xr[t + l * 128] : 0.f;
    for (int e = beg; e < end; e++) {
        int j = g_adj[e];
        float c = sc * g_adjw[e] * g_dinv[j];
        const float* xj = x + (size_t)j * F;
        #pragma unroll
        for (int l = 0; l < 4; l++) if (l < nf) acc[l] = fmaf(c, xj[t + l * 128], acc[l]);
    }
    float* hr = h + (size_t)node * F;
    #pragma unroll
    for (int l = 0; l < 4; l++) if (l < nf) hr[t + l * 128] = acc[l];
}

// ---------------- GEMM 128x128x8, 256 threads, 8x8/thread, bias+tanh ----------------
__global__ void gemm_tanh_kernel(const float* __restrict__ A, const float* __restrict__ W,
                                 const float* __restrict__ bias, float* __restrict__ C,
                                 int N, int K) {
    __shared__ float As[8][128];
    __shared__ float Bs[8][128];
    int tid = threadIdx.x;
    int m0 = blockIdx.y * 128, n0 = blockIdx.x * 128;
    int tx = tid & 15, ty = tid >> 4;
    int am = tid >> 1, ak = (tid & 1) * 4;
    int bk = tid >> 5, bn = (tid & 31) * 4;
    const float* Ap = A + (size_t)(m0 + am) * K + ak;
    const float* Bp = W + (size_t)bk * N + n0 + bn;
    float acc[8][8];
    #pragma unroll
    for (int i = 0; i < 8; i++)
        #pragma unroll
        for (int j = 0; j < 8; j++) acc[i][j] = 0.f;

    for (int kb = 0; kb < K; kb += 8) {
        float4 av = *(const float4*)(Ap + kb);
        float4 bv = *(const float4*)(Bp + (size_t)kb * N);
        As[ak + 0][am] = av.x; As[ak + 1][am] = av.y; As[ak + 2][am] = av.z; As[ak + 3][am] = av.w;
        *(float4*)&Bs[bk][bn] = bv;
        __syncthreads();
        #pragma unroll
        for (int k = 0; k < 8; k++) {
            float a[8], b[8];
            *(float4*)(a)     = *(const float4*)&As[k][ty * 4];
            *(float4*)(a + 4) = *(const float4*)&As[k][64 + ty * 4];
            *(float4*)(b)     = *(const float4*)&Bs[k][tx * 4];
            *(float4*)(b + 4) = *(const float4*)&Bs[k][64 + tx * 4];
            #pragma unroll
            for (int i = 0; i < 8; i++)
                #pragma unroll
                for (int j = 0; j < 8; j++) acc[i][j] = fmaf(a[i], b[j], acc[i][j]);
        }
        __syncthreads();
    }
    #pragma unroll
    for (int i = 0; i < 8; i++) {
        int m = m0 + ((i < 4) ? ty * 4 + i : 64 + ty * 4 + i - 4);
        #pragma unroll
        for (int j = 0; j < 8; j++) {
            int n = n0 + ((j < 4) ? tx * 4 + j : 64 + tx * 4 + j - 4);
            C[(size_t)m * N + n] = tanhf(acc[i][j] + bias[n]);
        }
    }
}

// ---------------- pooling + heads ----------------
__global__ void pool_kernel(const float* __restrict__ y) {
    int b = blockIdx.x, f = threadIdx.x;       // 512
    const float* p = y + (size_t)b * N_ND * H2 + f;
    float s = 0.f;
    for (int n = 0; n < N_ND; n++) s += p[(size_t)n * H2];
    g_pooled[b * H2 + f] = s * (1.0f / N_ND);
}
__global__ void dense_kernel(const float* __restrict__ Wd, const float* __restrict__ bd) {
    int b = blockIdx.x, t = threadIdx.x;       // 256
    __shared__ float p[H2];
    p[t] = g_pooled[b * H2 + t];
    p[t + 256] = g_pooled[b * H2 + t + 256];
    __syncthreads();
    float acc = bd[t];
    for (int k = 0; k < H2; k++) acc = fmaf(p[k], Wd[(size_t)k * H_IN + t], acc);
    g_hd[b * H_IN + t] = tanhf(acc);
}
__global__ void out_kernel(const float* __restrict__ Wo, const float* __restrict__ bo,
                           float* __restrict__ out) {
    int t = threadIdx.x;                        // 128
    int b = t >> 3, l = t & 7;
    const float* h = g_hd + b * H_IN;
    float acc = bo[l];
    for (int k = 0; k < H_IN; k++) acc = fmaf(h[k], Wo[k * 8 + l], acc);
    out[b * 8 + l] = acc;
}

// ---------------- launch ----------------
extern "C" void kernel_launch(void* const* d_in, const int* in_sizes, int n_in,
                              void* d_out, int out_size) {
    const float* features = (const float*)d_in[0];
    const float* W1 = (const float*)d_in[1];
    const float* b1 = (const float*)d_in[2];
    const float* W2 = (const float*)d_in[3];
    const float* b2 = (const float*)d_in[4];
    const float* W3 = (const float*)d_in[5];
    const float* b3 = (const float*)d_in[6];
    const float* Wd = (const float*)d_in[7];
    const float* bd = (const float*)d_in[8];
    const float* Wo = (const float*)d_in[9];
    const float* bo = (const float*)d_in[10];
    float* out = (float*)d_out;

    n2_kernel<<<NT / 8, 256>>>(features);
    dist_kernel<<<dim3(8, 8, B_GR), 256>>>(features);
    prim_kernel<<<B_GR, 256>>>();
    zero_kernel<<<NT / 256, 256>>>();
    count_kernel<<<NT / 256, 256>>>();
    scan_kernel<<<1, 256>>>();
    fill_kernel<<<NT / 256, 256>>>();
    dinv_kernel<<<NT / 256, 256>>>();

    // layer 1: prop on 256-dim input, gemm 256 -> 512
    prop_kernel<<<NT, 128>>>(features, g_bufA, H_IN);
    gemm_tanh_kernel<<<dim3(H2 / 128, NT / 128), 256>>>(g_bufA, W1, b1, g_bufB, H2, H_IN);
    // layer 2
    prop_kernel<<<NT, 128>>>(g_bufB, g_bufA, H2);
    gemm_tanh_kernel<<<dim3(H2 / 128, NT / 128), 256>>>(g_bufA, W2, b2, g_bufB, H2, H2);
    // layer 3
    prop_kernel<<<NT, 128>>>(g_bufB, g_bufA, H2);
    gemm_tanh_kernel<<<dim3(H2 / 128, NT / 128), 256>>>(g_bufA, W3, b3, g_bufB, H2, H2);

    pool_kernel<<<B_GR, H2>>>(g_bufB);
    dense_kernel<<<B_GR, 256>>>(Wd, bd);
    out_kernel<<<1, 128>>>(Wo, bo, out);
}

// round 5
// speedup vs baseline: 4.6181x; 4.6181x over previous
#include <cuda_runtime.h>
#include <cuda_bf16.h>
#include <math.h>
#include <stdint.h>

// ---------------- sizes ----------------
#define B_GR 16
#define N_ND 1024
#define H_IN 256
#define H2 512
#define NT (B_GR * N_ND)              // 16384
#define NEDGE (2 * (N_ND - 1) * B_GR)

// ---------------- scratch (device globals; no allocation) ----------------
__device__ __align__(16) float g_dist[B_GR * N_ND * N_ND];   // 64 MB
__device__ __align__(16) float g_n2[NT];
__device__ int   g_parent[NT];
__device__ float g_pw[NT];
__device__ int   g_cnt[NT];
__device__ int   g_indptr[NT + 1];
__device__ int   g_cursor[NT];
__device__ float g_degw[NT];
__device__ float g_dinv[NT];
__device__ int   g_adj[NEDGE];
__device__ float g_adjw[NEDGE];
__device__ __align__(16) float g_bufA[NT * H2];
__device__ __align__(16) float g_bufB[NT * H2];
__device__ float g_pooled[B_GR * H2];
__device__ float g_hd[B_GR * H_IN];
// bf16 split buffers
__device__ __align__(16) __nv_bfloat16 g_Ahi[NT * H2];
__device__ __align__(16) __nv_bfloat16 g_Alo[NT * H2];
__device__ __align__(16) __nv_bfloat16 g_W1hi[H2 * H_IN];
__device__ __align__(16) __nv_bfloat16 g_W1lo[H2 * H_IN];
__device__ __align__(16) __nv_bfloat16 g_W2hi[H2 * H2];
__device__ __align__(16) __nv_bfloat16 g_W2lo[H2 * H2];
__device__ __align__(16) __nv_bfloat16 g_W3hi[H2 * H2];
__device__ __align__(16) __nv_bfloat16 g_W3lo[H2 * H2];

// ---------------- n2 ----------------
__global__ void n2_kernel(const float* __restrict__ x) {
    int node = blockIdx.x * 8 + (threadIdx.x >> 5);
    int lane = threadIdx.x & 31;
    const float* r = x + (size_t)node * H_IN;
    float s = 0.f;
    #pragma unroll 4
    for (int k = lane; k < H_IN; k += 32) { float v = r[k]; s += v * v; }
    #pragma unroll
    for (int o = 16; o; o >>= 1) s += __shfl_xor_sync(0xffffffffu, s, o);
    if (lane == 0) g_n2[node] = s;
}

// ---------------- distance matrix (fp32, exact MST safety) ----------------
__global__ void dist_kernel(const float* __restrict__ X) {
    __shared__ float As[8][128];
    __shared__ float Bs[8][128];
    int g  = blockIdx.z;
    int i0 = blockIdx.y * 128, j0 = blockIdx.x * 128;
    const float* Xg = X + (size_t)g * N_ND * H_IN;
    int tid = threadIdx.x;
    int tx = tid & 15, ty = tid >> 4;
    int am = tid >> 1, ak = (tid & 1) * 4;
    const float* Ap = Xg + (size_t)(i0 + am) * H_IN + ak;
    const float* Bp = Xg + (size_t)(j0 + am) * H_IN + ak;
    float acc[8][8];
    #pragma unroll
    for (int i = 0; i < 8; i++)
        #pragma unroll
        for (int j = 0; j < 8; j++) acc[i][j] = 0.f;

    for (int kb = 0; kb < H_IN; kb += 8) {
        float4 av = *(const float4*)(Ap + kb);
        float4 bv = *(const float4*)(Bp + kb);
        As[ak + 0][am] = av.x; As[ak + 1][am] = av.y; As[ak + 2][am] = av.z; As[ak + 3][am] = av.w;
        Bs[ak + 0][am] = bv.x; Bs[ak + 1][am] = bv.y; Bs[ak + 2][am] = bv.z; Bs[ak + 3][am] = bv.w;
        __syncthreads();
        #pragma unroll
        for (int k = 0; k < 8; k++) {
            float a[8], b[8];
            *(float4*)(a)     = *(const float4*)&As[k][ty * 4];
            *(float4*)(a + 4) = *(const float4*)&As[k][64 + ty * 4];
            *(float4*)(b)     = *(const float4*)&Bs[k][tx * 4];
            *(float4*)(b + 4) = *(const float4*)&Bs[k][64 + tx * 4];
            #pragma unroll
            for (int i = 0; i < 8; i++)
                #pragma unroll
                for (int j = 0; j < 8; j++) acc[i][j] = fmaf(a[i], b[j], acc[i][j]);
        }
        __syncthreads();
    }
    float* D = g_dist + (size_t)g * N_ND * N_ND;
    #pragma unroll
    for (int i = 0; i < 8; i++) {
        int ii = (i < 4) ? ty * 4 + i : 64 + ty * 4 + i - 4;
        float n2i = g_n2[g * N_ND + i0 + ii];
        #pragma unroll
        for (int j = 0; j < 8; j++) {
            int jj = (j < 4) ? tx * 4 + j : 64 + tx * 4 + j - 4;
            float d2 = n2i + g_n2[g * N_ND + j0 + jj] - 2.0f * acc[i][j];
            D[(size_t)(i0 + ii) * N_ND + (j0 + jj)] = sqrtf(fmaxf(d2, 0.f));
        }
    }
}

// ---------------- Prim MST ----------------
__global__ void prim_kernel() {
    int g = blockIdx.x;
    int t = threadIdx.x;
    const float* D = g_dist + (size_t)g * N_ND * N_ND;
    __shared__ unsigned long long warpmin[8];
    __shared__ int s_v;
    __shared__ float s_w;

    float mind[4]; int par[4]; bool intree[4];
    {
        float4 d0 = *(const float4*)(D + t * 4);
        mind[0] = d0.x; mind[1] = d0.y; mind[2] = d0.z; mind[3] = d0.w;
        #pragma unroll
        for (int l = 0; l < 4; l++) { par[l] = 0; intree[l] = false; }
        if (t == 0) intree[0] = true;
    }
    int lane = t & 31, wid = t >> 5;

    for (int it = 0; it < N_ND - 1; ++it) {
        unsigned long long best = ~0ull;
        #pragma unroll
        for (int l = 0; l < 4; l++) {
            if (!intree[l]) {
                unsigned long long key =
                    ((unsigned long long)__float_as_uint(mind[l]) << 32) | (unsigned)(t * 4 + l);
                best = min(best, key);
            }
        }
        #pragma unroll
        for (int o = 16; o; o >>= 1)
            best = min(best, __shfl_xor_sync(0xffffffffu, best, o));
        if (lane == 0) warpmin[wid] = best;
        __syncthreads();
        if (wid == 0) {
            unsigned long long b2 = (lane < 8) ? warpmin[lane] : ~0ull;
            #pragma unroll
            for (int o = 4; o; o >>= 1)
                b2 = min(b2, __shfl_xor_sync(0xffffffffu, b2, o));
            if (lane == 0) {
                s_v = (int)(b2 & 0xffffffffu);
                s_w = __uint_as_float((unsigned)(b2 >> 32));
            }
        }
        __syncthreads();
        int v = s_v; float w = s_w;
        if ((v >> 2) == t) {
            int l = v & 3;
            g_parent[g * N_ND + v] = g * N_ND + par[l];
            g_pw[g * N_ND + v] = w;
            intree[l] = true;
        }
        float4 dv = *(const float4*)(D + (size_t)v * N_ND + t * 4);
        float dvv[4] = {dv.x, dv.y, dv.z, dv.w};
        #pragma unroll
        for (int l = 0; l < 4; l++) {
            if (dvv[l] < mind[l]) { mind[l] = dvv[l]; par[l] = v; }
        }
        __syncthreads();
    }
    if (t == 0) { g_parent[g * N_ND] = g * N_ND; g_pw[g * N_ND] = 0.f; }
}

// ---------------- CSR build ----------------
__global__ void zero_kernel() {
    int i = blockIdx.x * blockDim.x + threadIdx.x;
    g_cnt[i] = 0; g_degw[i] = 0.f;
}
__global__ void count_kernel() {
    int v = blockIdx.x * blockDim.x + threadIdx.x;
    if ((v & (N_ND - 1)) == 0) return;
    int p = g_parent[v];
    float w = g_pw[v];
    atomicAdd(&g_cnt[v], 1); atomicAdd(&g_cnt[p], 1);
    atomicAdd(&g_degw[v], w); atomicAdd(&g_degw[p], w);
}
__global__ void scan_kernel() {
    __shared__ int ps[256];
    int t = threadIdx.x;
    int base = t * 64;
    int s = 0;
    for (int i = 0; i < 64; i++) s += g_cnt[base + i];
    ps[t] = s;
    __syncthreads();
    for (int off = 1; off < 256; off <<= 1) {
        int v = (t >= off) ? ps[t - off] : 0;
        __syncthreads();
        ps[t] += v;
        __syncthreads();
    }
    int run = (t == 0) ? 0 : ps[t - 1];
    for (int i = 0; i < 64; i++) {
        g_indptr[base + i] = run;
        g_cursor[base + i] = run;
        run += g_cnt[base + i];
    }
    if (t == 255) g_indptr[NT] = run;
}
__global__ void fill_kernel() {
    int v = blockIdx.x * blockDim.x + threadIdx.x;
    if ((v & (N_ND - 1)) == 0) return;
    int p = g_parent[v];
    float w = g_pw[v];
    int pos = atomicAdd(&g_cursor[v], 1);
    g_adj[pos] = p; g_adjw[pos] = w;
    int pos2 = atomicAdd(&g_cursor[p], 1);
    g_adj[pos2] = v; g_adjw[pos2] = w;
}
__global__ void dinv_kernel() {
    int i = blockIdx.x * blockDim.x + threadIdx.x;
    g_dinv[i] = rsqrtf(g_degw[i] + 1.0f);
}

// ---------------- SSG propagation ----------------
__global__ void prop_kernel(const float* __restrict__ x, float* __restrict__ h, int F) {
    int node = blockIdx.x;
    int t = threadIdx.x;              // 128
    float di = g_dinv[node];
    float cs = 0.3f + 0.7f * di * di;
    float sc = 0.7f * di;
    int beg = g_indptr[node], end = g_indptr[node + 1];
    int nf = F >> 7;
    const float* xr = x + (size_t)node * F;
    float acc[4];
    #pragma unroll
    for (int l = 0; l < 4; l++) acc[l] = (l < nf) ? cs * xr[t + l * 128] : 0.f;
    for (int e = beg; e < end; e++) {
        int j = g_adj[e];
        float c = sc * g_adjw[e] * g_dinv[j];
        const float* xj = x + (size_t)j * F;
        #pragma unroll
        for (int l = 0; l < 4; l++) if (l < nf) acc[l] = fmaf(c, xj[t + l * 128], acc[l]);
    }
    float* hr = h + (size_t)node * F;
    #pragma unroll
    for (int l = 0; l < 4; l++) if (l < nf) hr[t + l * 128] = acc[l];
}

// ---------------- fp32 -> bf16 hi/lo split (elementwise) ----------------
__global__ void split_kernel(const float* __restrict__ x,
                             __nv_bfloat16* __restrict__ hi,
                             __nv_bfloat16* __restrict__ lo, int n4) {
    int i = blockIdx.x * blockDim.x + threadIdx.x;
    if (i >= n4) return;
    float4 v = ((const float4*)x)[i];
    __nv_bfloat16 h0 = __float2bfloat16(v.x), h1 = __float2bfloat16(v.y);
    __nv_bfloat16 h2 = __float2bfloat16(v.z), h3 = __float2bfloat16(v.w);
    __nv_bfloat16 l0 = __float2bfloat16(v.x - __bfloat162float(h0));
    __nv_bfloat16 l1 = __float2bfloat16(v.y - __bfloat162float(h1));
    __nv_bfloat16 l2 = __float2bfloat16(v.z - __bfloat162float(h2));
    __nv_bfloat16 l3 = __float2bfloat16(v.w - __bfloat162float(h3));
    ((__nv_bfloat162*)hi)[2 * i]     = __nv_bfloat162(h0, h1);
    ((__nv_bfloat162*)hi)[2 * i + 1] = __nv_bfloat162(h2, h3);
    ((__nv_bfloat162*)lo)[2 * i]     = __nv_bfloat162(l0, l1);
    ((__nv_bfloat162*)lo)[2 * i + 1] = __nv_bfloat162(l2, l3);
}

// ---------------- W [K,N] fp32 -> hi/lo transposed [N,K] bf16 ----------------
__global__ void wsplit_kernel(const float* __restrict__ W,
                              __nv_bfloat16* __restrict__ hiT,
                              __nv_bfloat16* __restrict__ loT, int K, int N) {
    __shared__ float s[32][33];
    int k0 = blockIdx.y * 32, n0 = blockIdx.x * 32;
    int tx = threadIdx.x, ty = threadIdx.y;   // 32 x 8
    #pragma unroll
    for (int j = 0; j < 32; j += 8)
        s[ty + j][tx] = W[(size_t)(k0 + ty + j) * N + n0 + tx];
    __syncthreads();
    #pragma unroll
    for (int j = 0; j < 32; j += 8) {
        float v = s[tx][ty + j];
        __nv_bfloat16 h = __float2bfloat16(v);
        __nv_bfloat16 l = __float2bfloat16(v - __bfloat162float(h));
        hiT[(size_t)(n0 + ty + j) * K + k0 + tx] = h;
        loT[(size_t)(n0 + ty + j) * K + k0 + tx] = l;
    }
}

// ---------------- mma.sync helpers ----------------
__device__ __forceinline__ uint32_t smem_u32(const void* p) {
    uint32_t r;
    asm("{ .reg .u64 t; cvta.to.shared.u64 t, %1; cvt.u32.u64 %0, t; }" : "=r"(r) : "l"(p));
    return r;
}
__device__ __forceinline__ void ldm_x4(uint32_t& r0, uint32_t& r1, uint32_t& r2, uint32_t& r3,
                                       uint32_t addr) {
    asm volatile("ldmatrix.sync.aligned.m8n8.x4.shared.b16 {%0,%1,%2,%3}, [%4];"
                 : "=r"(r0), "=r"(r1), "=r"(r2), "=r"(r3) : "r"(addr));
}
__device__ __forceinline__ void mma16816(float* c, const uint32_t* a, const uint32_t* b) {
    asm volatile("mma.sync.aligned.m16n8k16.row.col.f32.bf16.bf16.f32 "
                 "{%0,%1,%2,%3}, {%4,%5,%6,%7}, {%8,%9}, {%0,%1,%2,%3};"
                 : "+f"(c[0]), "+f"(c[1]), "+f"(c[2]), "+f"(c[3])
                 : "r"(a[0]), "r"(a[1]), "r"(a[2]), "r"(a[3]), "r"(b[0]), "r"(b[1]));
}

// ---------------- mma.sync GEMM: C[M,N] = tanh(A*B^T + bias), 3-term split ----------------
// A: [M,K] bf16 row-major (hi/lo), B: [N,K] bf16 row-major (hi/lo, pre-transposed).
// Tile 128x128, BK=32, 256 threads = 8 warps (4 in M x 2 in N), warp tile 32x64.
#define GPAD 8
#define GSTR (32 + GPAD)   // 40 bf16 = 80 bytes per row
__global__ void __launch_bounds__(256) gemm_mma_kernel(
    const __nv_bfloat16* __restrict__ Ahi, const __nv_bfloat16* __restrict__ Alo,
    const __nv_bfloat16* __restrict__ Bhi, const __nv_bfloat16* __restrict__ Blo,
    const float* __restrict__ bias, float* __restrict__ C, int N, int K)
{
    __shared__ __nv_bfloat16 sA[128 * GSTR];
    __shared__ __nv_bfloat16 sB[128 * GSTR];
    int tid = threadIdx.x, wid = tid >> 5, lane = tid & 31;
    int warpM = wid & 3, warpN = wid >> 2;
    int m0 = blockIdx.y * 128, n0 = blockIdx.x * 128;

    float acc[2][8][4];
    #pragma unroll
    for (int i = 0; i < 2; i++)
        #pragma unroll
        for (int j = 0; j < 8; j++)
            #pragma unroll
            for (int l = 0; l < 4; l++) acc[i][j][l] = 0.f;

    const __nv_bfloat16* Aps[3] = { Ahi, Ahi, Alo };
    const __nv_bfloat16* Bps[3] = { Bhi, Blo, Bhi };

    // ldmatrix source addresses (fixed per thread, offset by k-step)
    uint32_t aBase[2], bBase[4];
    #pragma unroll
    for (int mt = 0; mt < 2; mt++)
        aBase[mt] = smem_u32(&sA[(warpM * 32 + mt * 16 + (lane & 15)) * GSTR + (lane >> 4) * 8]);
    #pragma unroll
    for (int nt2 = 0; nt2 < 4; nt2++)
        bBase[nt2] = smem_u32(&sB[(warpN * 64 + nt2 * 16 + (lane & 15)) * GSTR + (lane >> 4) * 8]);

    int lrow = tid >> 2, lch = tid & 3;

    for (int pass = 0; pass < 3; pass++) {
        const __nv_bfloat16* Ap = Aps[pass] + (size_t)m0 * K;
        const __nv_bfloat16* Bp = Bps[pass] + (size_t)n0 * K;
        for (int k0 = 0; k0 < K; k0 += 32) {
            // load 128x32 bf16 tiles: 2 sweeps of 64 rows x 4 16B-chunks
            #pragma unroll
            for (int h = 0; h < 2; h++) {
                int row = h * 64 + lrow;
                *(uint4*)&sA[row * GSTR + lch * 8] =
                    *(const uint4*)(Ap + (size_t)row * K + k0 + lch * 8);
                *(uint4*)&sB[row * GSTR + lch * 8] =
                    *(const uint4*)(Bp + (size_t)row * K + k0 + lch * 8);
            }
            __syncthreads();
            #pragma unroll
            for (int ks = 0; ks < 2; ks++) {
                uint32_t koff = ks * 16 * 2;  // bytes: 16 bf16
                uint32_t a[2][4];
                #pragma unroll
                for (int mt = 0; mt < 2; mt++)
                    ldm_x4(a[mt][0], a[mt][1], a[mt][2], a[mt][3], aBase[mt] + koff);
                uint32_t b[8][2];
                #pragma unroll
                for (int nt2 = 0; nt2 < 4; nt2++) {
                    uint32_t m0r, m1r, m2r, m3r;
                    ldm_x4(m0r, m1r, m2r, m3r, bBase[nt2] + koff);
                    b[nt2 * 2 + 0][0] = m0r; b[nt2 * 2 + 0][1] = m2r;
                    b[nt2 * 2 + 1][0] = m1r; b[nt2 * 2 + 1][1] = m3r;
                }
                #pragma unroll
                for (int mt = 0; mt < 2; mt++)
                    #pragma unroll
                    for (int nt = 0; nt < 8; nt++)
                        mma16816(acc[mt][nt], a[mt], b[nt]);
            }
            __syncthreads();
        }
    }

    // epilogue
    #pragma unroll
    for (int mt = 0; mt < 2; mt++) {
        int r0 = m0 + warpM * 32 + mt * 16 + (lane >> 2);
        #pragma unroll
        for (int nt = 0; nt < 8; nt++) {
            int c0 = n0 + warpN * 64 + nt * 8 + (lane & 3) * 2;
            float bv0 = bias[c0], bv1 = bias[c0 + 1];
            C[(size_t)r0 * N + c0]           = tanhf(acc[mt][nt][0] + bv0);
            C[(size_t)r0 * N + c0 + 1]       = tanhf(acc[mt][nt][1] + bv1);
            C[(size_t)(r0 + 8) * N + c0]     = tanhf(acc[mt][nt][2] + bv0);
            C[(size_t)(r0 + 8) * N + c0 + 1] = tanhf(acc[mt][nt][3] + bv1);
        }
    }
}

// ---------------- pooling + heads ----------------
__global__ void pool_kernel(const float* __restrict__ y) {
    int b = blockIdx.x, f = threadIdx.x;
    const float* p = y + (size_t)b * N_ND * H2 + f;
    float s = 0.f;
    for (int n = 0; n < N_ND; n++) s += p[(size_t)n * H2];
    g_pooled[b * H2 + f] = s * (1.0f / N_ND);
}
__global__ void dense_kernel(const float* __restrict__ Wd, const float* __restrict__ bd) {
    int b = blockIdx.x, t = threadIdx.x;
    __shared__ float p[H2];
    p[t] = g_pooled[b * H2 + t];
    p[t + 256] = g_pooled[b * H2 + t + 256];
    __syncthreads();
    float acc = bd[t];
    for (int k = 0; k < H2; k++) acc = fmaf(p[k], Wd[(size_t)k * H_IN + t], acc);
    g_hd[b * H_IN + t] = tanhf(acc);
}
__global__ void out_kernel(const float* __restrict__ Wo, const float* __restrict__ bo,
                           float* __restrict__ out) {
    int t = threadIdx.x;
    int b = t >> 3, l = t & 7;
    const float* h = g_hd + b * H_IN;
    float acc = bo[l];
    for (int k = 0; k < H_IN; k++) acc = fmaf(h[k], Wo[k * 8 + l], acc);
    out[b * 8 + l] = acc;
}

// ---------------- launch ----------------
extern "C" void kernel_launch(void* const* d_in, const int* in_sizes, int n_in,
                              void* d_out, int out_size) {
    const float* features = (const float*)d_in[0];
    const float* W1 = (const float*)d_in[1];
    const float* b1 = (const float*)d_in[2];
    const float* W2 = (const float*)d_in[3];
    const float* b2 = (const float*)d_in[4];
    const float* W3 = (const float*)d_in[5];
    const float* b3 = (const float*)d_in[6];
    const float* Wd = (const float*)d_in[7];
    const float* bd = (const float*)d_in[8];
    const float* Wo = (const float*)d_in[9];
    const float* bo = (const float*)d_in[10];
    float* out = (float*)d_out;

    __nv_bfloat16 *pAhi, *pAlo, *pW1hi, *pW1lo, *pW2hi, *pW2lo, *pW3hi, *pW3lo;
    float *pbufA, *pbufB;
    cudaGetSymbolAddress((void**)&pAhi, g_Ahi);
    cudaGetSymbolAddress((void**)&pAlo, g_Alo);
    cudaGetSymbolAddress((void**)&pW1hi, g_W1hi);
    cudaGetSymbolAddress((void**)&pW1lo, g_W1lo);
    cudaGetSymbolAddress((void**)&pW2hi, g_W2hi);
    cudaGetSymbolAddress((void**)&pW2lo, g_W2lo);
    cudaGetSymbolAddress((void**)&pW3hi, g_W3hi);
    cudaGetSymbolAddress((void**)&pW3lo, g_W3lo);
    cudaGetSymbolAddress((void**)&pbufA, g_bufA);
    cudaGetSymbolAddress((void**)&pbufB, g_bufB);

    n2_kernel<<<NT / 8, 256>>>(features);
    dist_kernel<<<dim3(8, 8, B_GR), 256>>>(features);
    prim_kernel<<<B_GR, 256>>>();
    zero_kernel<<<NT / 256, 256>>>();
    count_kernel<<<NT / 256, 256>>>();
    scan_kernel<<<1, 256>>>();
    fill_kernel<<<NT / 256, 256>>>();
    dinv_kernel<<<NT / 256, 256>>>();

    // weight conversions (transposed hi/lo)
    wsplit_kernel<<<dim3(H2 / 32, H_IN / 32), dim3(32, 8)>>>(W1, pW1hi, pW1lo, H_IN, H2);
    wsplit_kernel<<<dim3(H2 / 32, H2 / 32), dim3(32, 8)>>>(W2, pW2hi, pW2lo, H2, H2);
    wsplit_kernel<<<dim3(H2 / 32, H2 / 32), dim3(32, 8)>>>(W3, pW3hi, pW3lo, H2, H2);

    // layer 1
    prop_kernel<<<NT, 128>>>(features, pbufA, H_IN);
    split_kernel<<<(NT * H_IN / 4 + 255) / 256, 256>>>(pbufA, pAhi, pAlo, NT * H_IN / 4);
    gemm_mma_kernel<<<dim3(H2 / 128, NT / 128), 256>>>(pAhi, pAlo, pW1hi, pW1lo, b1, pbufB, H2, H_IN);
    // layer 2
    prop_kernel<<<NT, 128>>>(pbufB, pbufA, H2);
    split_kernel<<<(NT * H2 / 4 + 255) / 256, 256>>>(pbufA, pAhi, pAlo, NT * H2 / 4);
    gemm_mma_kernel<<<dim3(H2 / 128, NT / 128), 256>>>(pAhi, pAlo, pW2hi, pW2lo, b2, pbufB, H2, H2);
    // layer 3
    prop_kernel<<<NT, 128>>>(pbufB, pbufA, H2);
    split_kernel<<<(NT * H2 / 4 + 255) / 256, 256>>>(pbufA, pAhi, pAlo, NT * H2 / 4);
    gemm_mma_kernel<<<dim3(H2 / 128, NT / 128), 256>>>(pAhi, pAlo, pW3hi, pW3lo, b3, pbufB, H2, H2);

    pool_kernel<<<B_GR, H2>>>(pbufB);
    dense_kernel<<<B_GR, 256>>>(Wd, bd);
    out_kernel<<<1, 128>>>(Wo, bo, out);
}